// round 1
// baseline (speedup 1.0000x reference)
#include <cuda_runtime.h>
#include <math.h>

#define B_DIM 4096
#define IN_DIM 1024
#define H_DIM 1024
#define K_DIM 2048   // IN + H
#define N_DIM 4096   // 4*H

// Scratch (device globals; no allocation allowed in kernel_launch)
__device__ float g_A[(size_t)B_DIM * K_DIM];      // [B, K]   = [x | h]
__device__ float g_W[(size_t)N_DIM * K_DIM];      // [4H, K]  = [Wx | Wh] in gate order f,i,o,c
__device__ float g_bias[N_DIM];                   // bx + bh
__device__ float g_gates[(size_t)B_DIM * N_DIM];  // activated gates

// ---------------------------------------------------------------------------
// Fast activations (MUFU.EX2-based, ~1e-6 rel err — negligible vs 1e-3 gate)
// ---------------------------------------------------------------------------
__device__ __forceinline__ float fast_sigmoid(float x) {
    return 1.0f / (1.0f + __expf(-x));
}
__device__ __forceinline__ float fast_tanh(float x) {
    float ax = fabsf(x);
    float e  = __expf(-2.0f * ax);          // in (0, 1], never overflows
    float t  = (1.0f - e) / (1.0f + e);
    return copysignf(t, x);
}

// ---------------------------------------------------------------------------
// Pack A = [x | h]  (float4 vectorized)
// ---------------------------------------------------------------------------
__global__ void pack_A_kernel(const float4* __restrict__ x, const float4* __restrict__ h) {
    int i = blockIdx.x * blockDim.x + threadIdx.x;   // over B*K/4
    const int K4 = K_DIM / 4, IN4 = IN_DIM / 4;
    int b  = i / K4;
    int k4 = i - b * K4;
    float4 v = (k4 < IN4) ? x[b * IN4 + k4] : h[b * IN4 + (k4 - IN4)];
    reinterpret_cast<float4*>(g_A)[i] = v;
}

// ---------------------------------------------------------------------------
// Pack W = [Wx | Wh] concatenated along K, rows in gate order f,i,o,c
// ---------------------------------------------------------------------------
__global__ void pack_W_kernel(const float4* __restrict__ Wxf, const float4* __restrict__ Wxi,
                              const float4* __restrict__ Wxo, const float4* __restrict__ Wxc,
                              const float4* __restrict__ Whf, const float4* __restrict__ Whi,
                              const float4* __restrict__ Who, const float4* __restrict__ Whc) {
    int i = blockIdx.x * blockDim.x + threadIdx.x;   // over N*K/4
    const int K4 = K_DIM / 4, IN4 = IN_DIM / 4;
    int r  = i / K4;
    int k4 = i - r * K4;
    int g  = r >> 10;
    int j  = r & 1023;
    const float4* Wx[4] = {Wxf, Wxi, Wxo, Wxc};
    const float4* Wh[4] = {Whf, Whi, Who, Whc};
    float4 v = (k4 < IN4) ? Wx[g][j * IN4 + k4] : Wh[g][j * IN4 + (k4 - IN4)];
    reinterpret_cast<float4*>(g_W)[i] = v;
}

__global__ void bias_kernel(const float* __restrict__ bxf, const float* __restrict__ bxi,
                            const float* __restrict__ bxo, const float* __restrict__ bxc,
                            const float* __restrict__ bhf, const float* __restrict__ bhi,
                            const float* __restrict__ bho, const float* __restrict__ bhc) {
    int r = blockIdx.x * blockDim.x + threadIdx.x;
    int g = r >> 10;
    int j = r & 1023;
    const float* bx[4] = {bxf, bxi, bxo, bxc};
    const float* bh[4] = {bhf, bhi, bho, bhc};
    g_bias[r] = bx[g][j] + bh[g][j];
}

// ---------------------------------------------------------------------------
// fp32 SIMT GEMM: gates[b, r] = act( sum_k A[b,k] * W[r,k] + bias[r] )
// 128x128x16 tiles, 256 threads, 8x8 microtile, double-buffered smem,
// XOR-swizzled transposed tiles (conflict-free stores + vectorized loads).
// Activation fused (each 128-wide column tile lies in exactly one gate).
// ---------------------------------------------------------------------------
#define BM 128
#define BN 128
#define BK 16

__global__ __launch_bounds__(256, 2)
void gemm_gates_kernel() {
    __shared__ float As[2][BK][BM];
    __shared__ float Ws[2][BK][BN];

    const float* __restrict__ A = g_A;
    const float* __restrict__ W = g_W;

    const int bm  = blockIdx.y * BM;
    const int bn  = blockIdx.x * BN;
    const int tid = threadIdx.x;
    const int tx  = tid & 15;       // 0..15 -> output cols tx*8..tx*8+7
    const int ty  = tid >> 4;       // 0..15 -> output rows ty*8..ty*8+7

    // Global-load assignment: two float4 per matrix per thread
    const int r0  = tid >> 2;            // rows 0..63
    const int r1  = r0 + 64;             // rows 64..127
    const int kq  = (tid & 3) << 2;      // 0,4,8,12
    const int swz = (kq >> 2) << 3;      // XOR swizzle for this k-quad

    const float* Aptr0 = A + (size_t)(bm + r0) * K_DIM + kq;
    const float* Aptr1 = A + (size_t)(bm + r1) * K_DIM + kq;
    const float* Wptr0 = W + (size_t)(bn + r0) * K_DIM + kq;
    const float* Wptr1 = W + (size_t)(bn + r1) * K_DIM + kq;

    float acc[8][8];
    #pragma unroll
    for (int i = 0; i < 8; i++)
        #pragma unroll
        for (int j = 0; j < 8; j++) acc[i][j] = 0.0f;

    // Prologue: tile 0 -> smem buffer 0
    float4 a0 = *reinterpret_cast<const float4*>(Aptr0);
    float4 a1 = *reinterpret_cast<const float4*>(Aptr1);
    float4 w0 = *reinterpret_cast<const float4*>(Wptr0);
    float4 w1 = *reinterpret_cast<const float4*>(Wptr1);
    {
        const int ra0 = r0 ^ swz, ra1 = r1 ^ swz;
        As[0][kq + 0][ra0] = a0.x; As[0][kq + 1][ra0] = a0.y;
        As[0][kq + 2][ra0] = a0.z; As[0][kq + 3][ra0] = a0.w;
        As[0][kq + 0][ra1] = a1.x; As[0][kq + 1][ra1] = a1.y;
        As[0][kq + 2][ra1] = a1.z; As[0][kq + 3][ra1] = a1.w;
        Ws[0][kq + 0][ra0] = w0.x; Ws[0][kq + 1][ra0] = w0.y;
        Ws[0][kq + 2][ra0] = w0.z; Ws[0][kq + 3][ra0] = w0.w;
        Ws[0][kq + 0][ra1] = w1.x; Ws[0][kq + 1][ra1] = w1.y;
        Ws[0][kq + 2][ra1] = w1.z; Ws[0][kq + 3][ra1] = w1.w;
    }
    __syncthreads();

    const int ntiles = K_DIM / BK;   // 128
    int buf = 0;

    for (int t = 0; t < ntiles; t++) {
        // Prefetch next tile into registers (overlaps with compute below)
        if (t + 1 < ntiles) {
            const int koff = (t + 1) * BK;
            a0 = *reinterpret_cast<const float4*>(Aptr0 + koff);
            a1 = *reinterpret_cast<const float4*>(Aptr1 + koff);
            w0 = *reinterpret_cast<const float4*>(Wptr0 + koff);
            w1 = *reinterpret_cast<const float4*>(Wptr1 + koff);
        }

        // Compute on current buffer
        #pragma unroll
        for (int k = 0; k < BK; k++) {
            const int s = (k >> 2) << 3;
            const float* arow = &As[buf][k][0];
            const float* wrow = &Ws[buf][k][0];
            const int am = (ty * 8) ^ s;
            const int wm = (tx * 8) ^ s;
            float4 af0 = *reinterpret_cast<const float4*>(arow + am);
            float4 af1 = *reinterpret_cast<const float4*>(arow + am + 4);
            float4 wf0 = *reinterpret_cast<const float4*>(wrow + wm);
            float4 wf1 = *reinterpret_cast<const float4*>(wrow + wm + 4);
            float av[8] = {af0.x, af0.y, af0.z, af0.w, af1.x, af1.y, af1.z, af1.w};
            float wv[8] = {wf0.x, wf0.y, wf0.z, wf0.w, wf1.x, wf1.y, wf1.z, wf1.w};
            #pragma unroll
            for (int i = 0; i < 8; i++)
                #pragma unroll
                for (int j = 0; j < 8; j++)
                    acc[i][j] += av[i] * wv[j];
        }

        // Store prefetched tile into the other buffer
        if (t + 1 < ntiles) {
            buf ^= 1;
            const int ra0 = r0 ^ swz, ra1 = r1 ^ swz;
            As[buf][kq + 0][ra0] = a0.x; As[buf][kq + 1][ra0] = a0.y;
            As[buf][kq + 2][ra0] = a0.z; As[buf][kq + 3][ra0] = a0.w;
            As[buf][kq + 0][ra1] = a1.x; As[buf][kq + 1][ra1] = a1.y;
            As[buf][kq + 2][ra1] = a1.z; As[buf][kq + 3][ra1] = a1.w;
            Ws[buf][kq + 0][ra0] = w0.x; Ws[buf][kq + 1][ra0] = w0.y;
            Ws[buf][kq + 2][ra0] = w0.z; Ws[buf][kq + 3][ra0] = w0.w;
            Ws[buf][kq + 0][ra1] = w1.x; Ws[buf][kq + 1][ra1] = w1.y;
            Ws[buf][kq + 2][ra1] = w1.z; Ws[buf][kq + 3][ra1] = w1.w;
        }
        __syncthreads();
    }

    // Fused bias + activation epilogue (gate uniform per column-block)
    const int gate = bn >> 10;            // 0=f, 1=i, 2=o, 3=c~
    float bcol[8];
    #pragma unroll
    for (int j = 0; j < 8; j++) bcol[j] = g_bias[bn + tx * 8 + j];

    float* Cbase = g_gates + (size_t)(bm + ty * 8) * N_DIM + bn + tx * 8;
    #pragma unroll
    for (int i = 0; i < 8; i++) {
        float v[8];
        #pragma unroll
        for (int j = 0; j < 8; j++) {
            float z = acc[i][j] + bcol[j];
            v[j] = (gate == 3) ? fast_tanh(z) : fast_sigmoid(z);
        }
        *reinterpret_cast<float4*>(Cbase + (size_t)i * N_DIM)     = make_float4(v[0], v[1], v[2], v[3]);
        *reinterpret_cast<float4*>(Cbase + (size_t)i * N_DIM + 4) = make_float4(v[4], v[5], v[6], v[7]);
    }
}

// ---------------------------------------------------------------------------
// Final elementwise: ct = f*c + c~*i ; ht = tanh(ct)*o
// out = [ct (B*H floats) | ht (B*H floats)]
// ---------------------------------------------------------------------------
__global__ void lstm_final_kernel(const float4* __restrict__ c, float* __restrict__ out) {
    int i = blockIdx.x * blockDim.x + threadIdx.x;   // over B*H/4
    int b  = i >> 8;                                 // H/4 = 256 float4 per gate row
    int j4 = i & 255;
    const float4* grow = reinterpret_cast<const float4*>(g_gates + (size_t)b * N_DIM);
    float4 f  = grow[j4];
    float4 ig = grow[256 + j4];
    float4 o  = grow[512 + j4];
    float4 cu = grow[768 + j4];
    float4 cp = c[i];

    float4 ct, ht;
    ct.x = f.x * cp.x + cu.x * ig.x;
    ct.y = f.y * cp.y + cu.y * ig.y;
    ct.z = f.z * cp.z + cu.z * ig.z;
    ct.w = f.w * cp.w + cu.w * ig.w;
    ht.x = fast_tanh(ct.x) * o.x;
    ht.y = fast_tanh(ct.y) * o.y;
    ht.z = fast_tanh(ct.z) * o.z;
    ht.w = fast_tanh(ct.w) * o.w;

    reinterpret_cast<float4*>(out)[i] = ct;
    reinterpret_cast<float4*>(out + (size_t)B_DIM * H_DIM)[i] = ht;
}

// ---------------------------------------------------------------------------
// kernel_launch
// Input order: x, c, h, Wxf, bxf, Whf, bhf, Wxi, bxi, Whi, bhi,
//              Wxo, bxo, Who, bho, Wxc, bxc, Whc, bhc
// ---------------------------------------------------------------------------
extern "C" void kernel_launch(void* const* d_in, const int* in_sizes, int n_in,
                              void* d_out, int out_size) {
    const float* x   = (const float*)d_in[0];
    const float* c   = (const float*)d_in[1];
    const float* h   = (const float*)d_in[2];
    const float* Wxf = (const float*)d_in[3];
    const float* bxf = (const float*)d_in[4];
    const float* Whf = (const float*)d_in[5];
    const float* bhf = (const float*)d_in[6];
    const float* Wxi = (const float*)d_in[7];
    const float* bxi = (const float*)d_in[8];
    const float* Whi = (const float*)d_in[9];
    const float* bhi = (const float*)d_in[10];
    const float* Wxo = (const float*)d_in[11];
    const float* bxo = (const float*)d_in[12];
    const float* Who = (const float*)d_in[13];
    const float* bho = (const float*)d_in[14];
    const float* Wxc = (const float*)d_in[15];
    const float* bxc = (const float*)d_in[16];
    const float* Whc = (const float*)d_in[17];
    const float* bhc = (const float*)d_in[18];

    // Pack activations and weights
    pack_A_kernel<<<(B_DIM * K_DIM / 4) / 256, 256>>>(
        (const float4*)x, (const float4*)h);
    pack_W_kernel<<<(N_DIM * K_DIM / 4) / 256, 256>>>(
        (const float4*)Wxf, (const float4*)Wxi, (const float4*)Wxo, (const float4*)Wxc,
        (const float4*)Whf, (const float4*)Whi, (const float4*)Who, (const float4*)Whc);
    bias_kernel<<<N_DIM / 256, 256>>>(bxf, bxi, bxo, bxc, bhf, bhi, bho, bhc);

    // Fused GEMM + bias + gate activation
    dim3 grid(N_DIM / BN, B_DIM / BM);
    gemm_gates_kernel<<<grid, 256>>>();

    // Final elementwise LSTM update
    lstm_final_kernel<<<(B_DIM * H_DIM / 4) / 256, 256>>>(
        (const float4*)c, (float*)d_out);
}

// round 3
// speedup vs baseline: 2.6341x; 2.6341x over previous
#include <cuda_runtime.h>
#include <cuda_bf16.h>
#include <cstdint>
#include <math.h>

#define B_DIM 4096
#define IN_DIM 1024
#define H_DIM 1024
#define K_DIM 2048   // IN + H
#define N_DIM 4096   // 4*H, gate-interleaved: col n -> gate n&3, hidden n>>2

#define BM 128
#define BN 128
#define KC 32
#define NCHUNK (K_DIM / KC)     // 64

// SMEM tile geometry: rows of 32 bf16 (64B) padded to 80B for conflict-free
// ldmatrix (bank start = 20*r mod 32, distinct for r=0..7) and cp.async.
#define ROWB 80
#define TILEB (128 * ROWB)            // 10240 B per matrix
#define OFF_AHI 0
#define OFF_ALO (TILEB)
#define OFF_WHI (2 * TILEB)
#define OFF_WLO (3 * TILEB)
#define BUFB   (4 * TILEB)            // 40960 B
#define SMEM_TOTAL (2 * BUFB)         // 81920 B

// ---------------------------------------------------------------------------
// Device scratch
// ---------------------------------------------------------------------------
__device__ __nv_bfloat16 g_Ahi[(size_t)B_DIM * K_DIM];
__device__ __nv_bfloat16 g_Alo[(size_t)B_DIM * K_DIM];
__device__ __nv_bfloat16 g_Whi[(size_t)N_DIM * K_DIM];
__device__ __nv_bfloat16 g_Wlo[(size_t)N_DIM * K_DIM];
__device__ float g_biasp[N_DIM];

// ---------------------------------------------------------------------------
// PTX helpers (baseline PTX only: works on compute_103 virtual arch)
// ---------------------------------------------------------------------------
__device__ __forceinline__ uint32_t smem_u32(const void* p) {
    uint32_t a;
    asm("{ .reg .u64 t; cvta.to.shared.u64 t, %1; cvt.u32.u64 %0, t; }" : "=r"(a) : "l"(p));
    return a;
}
__device__ __forceinline__ void cp_async16(uint32_t dst, const void* src) {
    asm volatile("cp.async.cg.shared.global [%0], [%1], 16;" :: "r"(dst), "l"(src));
}
#define CP_COMMIT()  asm volatile("cp.async.commit_group;" ::: "memory")
#define CP_WAIT(N)   asm volatile("cp.async.wait_group %0;" :: "n"(N) : "memory")

__device__ __forceinline__ void ldsm4(uint32_t* r, uint32_t addr) {
    asm volatile("ldmatrix.sync.aligned.m8n8.x4.shared.b16 {%0,%1,%2,%3}, [%4];"
        : "=r"(r[0]), "=r"(r[1]), "=r"(r[2]), "=r"(r[3]) : "r"(addr));
}
__device__ __forceinline__ void mma16816(float* d, const uint32_t* a, const uint32_t* b) {
    asm volatile("mma.sync.aligned.m16n8k16.row.col.f32.bf16.bf16.f32 "
        "{%0,%1,%2,%3}, {%4,%5,%6,%7}, {%8,%9}, {%0,%1,%2,%3};"
        : "+f"(d[0]), "+f"(d[1]), "+f"(d[2]), "+f"(d[3])
        : "r"(a[0]), "r"(a[1]), "r"(a[2]), "r"(a[3]), "r"(b[0]), "r"(b[1]));
}

__device__ __forceinline__ float fast_sigmoid(float x) { return 1.0f / (1.0f + __expf(-x)); }
__device__ __forceinline__ float fast_tanh(float x) {
    float e = __expf(-2.0f * fabsf(x));
    return copysignf((1.0f - e) / (1.0f + e), x);
}

// ---------------------------------------------------------------------------
// Pack A = [x | h] into bf16 hi/lo split
// ---------------------------------------------------------------------------
__global__ void pack_A_kernel(const float4* __restrict__ x, const float4* __restrict__ h) {
    int i = blockIdx.x * blockDim.x + threadIdx.x;   // over B*K/4
    int b = i >> 9, k4 = i & 511;
    float4 v = (k4 < 256) ? x[b * 256 + k4] : h[b * 256 + (k4 - 256)];
    float vs[4] = {v.x, v.y, v.z, v.w};
    __nv_bfloat16 hi[4], lo[4];
    #pragma unroll
    for (int e = 0; e < 4; e++) {
        hi[e] = __float2bfloat16(vs[e]);
        lo[e] = __float2bfloat16(vs[e] - __bfloat162float(hi[e]));
    }
    __nv_bfloat162* Ah = reinterpret_cast<__nv_bfloat162*>(g_Ahi);
    __nv_bfloat162* Al = reinterpret_cast<__nv_bfloat162*>(g_Alo);
    Ah[i * 2]     = __halves2bfloat162(hi[0], hi[1]);
    Ah[i * 2 + 1] = __halves2bfloat162(hi[2], hi[3]);
    Al[i * 2]     = __halves2bfloat162(lo[0], lo[1]);
    Al[i * 2 + 1] = __halves2bfloat162(lo[2], lo[3]);
}

// ---------------------------------------------------------------------------
// Pack W gate-interleaved (col n -> gate n&3, hidden n>>2), K-concat, hi/lo
// ---------------------------------------------------------------------------
__global__ void pack_W_kernel(const float4* __restrict__ Wxf, const float4* __restrict__ Wxi,
                              const float4* __restrict__ Wxo, const float4* __restrict__ Wxc,
                              const float4* __restrict__ Whf, const float4* __restrict__ Whi,
                              const float4* __restrict__ Who, const float4* __restrict__ Whc) {
    int i = blockIdx.x * blockDim.x + threadIdx.x;   // over N*K/4
    int n = i >> 9, k4 = i & 511;
    int g = n & 3, j = n >> 2;
    const float4* Wx[4] = {Wxf, Wxi, Wxo, Wxc};
    const float4* Wh[4] = {Whf, Whi, Who, Whc};
    float4 v = (k4 < 256) ? Wx[g][j * 256 + k4] : Wh[g][j * 256 + (k4 - 256)];
    float vs[4] = {v.x, v.y, v.z, v.w};
    __nv_bfloat16 hi[4], lo[4];
    #pragma unroll
    for (int e = 0; e < 4; e++) {
        hi[e] = __float2bfloat16(vs[e]);
        lo[e] = __float2bfloat16(vs[e] - __bfloat162float(hi[e]));
    }
    __nv_bfloat162* Wh2 = reinterpret_cast<__nv_bfloat162*>(g_Whi);
    __nv_bfloat162* Wl2 = reinterpret_cast<__nv_bfloat162*>(g_Wlo);
    Wh2[i * 2]     = __halves2bfloat162(hi[0], hi[1]);
    Wh2[i * 2 + 1] = __halves2bfloat162(hi[2], hi[3]);
    Wl2[i * 2]     = __halves2bfloat162(lo[0], lo[1]);
    Wl2[i * 2 + 1] = __halves2bfloat162(lo[2], lo[3]);
}

__global__ void pack_bias_kernel(const float* __restrict__ bxf, const float* __restrict__ bxi,
                                 const float* __restrict__ bxo, const float* __restrict__ bxc,
                                 const float* __restrict__ bhf, const float* __restrict__ bhi,
                                 const float* __restrict__ bho, const float* __restrict__ bhc) {
    int n = blockIdx.x * blockDim.x + threadIdx.x;
    int g = n & 3, j = n >> 2;
    const float* bx[4] = {bxf, bxi, bxo, bxc};
    const float* bh[4] = {bhf, bhi, bho, bhc};
    g_biasp[n] = bx[g][j] + bh[g][j];
}

// ---------------------------------------------------------------------------
// HMMA GEMM + fused LSTM epilogue.
// 8 warps: warp grid 2(M) x 4(N); warp tile 64x32; mma m16n8k16 bf16.
// acc += Ahi*Whi + Alo*Whi + Ahi*Wlo  (fp32), bias+activations+LSTM in epilogue.
// ---------------------------------------------------------------------------
__global__ void __launch_bounds__(256, 2)
lstm_gemm_kernel(const float* __restrict__ c_in, float* __restrict__ out) {
    extern __shared__ char smem[];
    const uint32_t sb = smem_u32(smem);
    const int tid  = threadIdx.x;
    const int lane = tid & 31;
    const int wid  = tid >> 5;
    const int wm   = wid >> 2;         // 0..1
    const int wn   = wid & 3;          // 0..3
    const int m0   = blockIdx.y * BM;
    const int n0   = blockIdx.x * BN;

    // ---- chunk loader: 8 x 16B cp.async per thread ----
    auto load_chunk = [&](int t, int b) {
        const uint32_t base = sb + b * BUFB;
        const int r = tid >> 2;            // 0..63
        const int s = tid & 3;             // 0..3 (16B segment)
        const int kg = t * KC + s * 8;     // global k of this segment
        #pragma unroll
        for (int q = 0; q < 2; q++) {      // rows r and r+64
            const int rr = r + q * 64;
            const uint32_t so = (uint32_t)(rr * ROWB + s * 16);
            const size_t aoff = (size_t)(m0 + rr) * K_DIM + kg;
            const size_t woff = (size_t)(n0 + rr) * K_DIM + kg;
            cp_async16(base + OFF_AHI + so, g_Ahi + aoff);
            cp_async16(base + OFF_ALO + so, g_Alo + aoff);
            cp_async16(base + OFF_WHI + so, g_Whi + woff);
            cp_async16(base + OFF_WLO + so, g_Wlo + woff);
        }
        CP_COMMIT();
    };

    float acc[4][4][4];
    #pragma unroll
    for (int i = 0; i < 4; i++)
        #pragma unroll
        for (int j = 0; j < 4; j++)
            #pragma unroll
            for (int e = 0; e < 4; e++) acc[i][j][e] = 0.0f;

    load_chunk(0, 0);
    load_chunk(1, 1);

    // ldmatrix lane addressing (within a 16x16 bf16 fragment)
    const int a_row = lane & 15;                 // A: row within 16
    const int a_col = (lane >> 4) * 16;          // byte offset: 8-col half
    const int b_row = (lane & 7) + (lane >> 4) * 8;   // W(n) row within 16
    const int b_col = ((lane >> 3) & 1) * 16;         // byte offset: k half

    for (int t = 0; t < NCHUNK; t++) {
        const int b = t & 1;
        if (t < NCHUNK - 2) CP_WAIT(1); else CP_WAIT(0);
        __syncthreads();

        const uint32_t base = sb + b * BUFB;
        #pragma unroll
        for (int h = 0; h < 2; h++) {            // two k16 steps per 32-chunk
            uint32_t ah[16], al[16], bb[8];
            #pragma unroll
            for (int mi = 0; mi < 4; mi++) {
                uint32_t ad = base + OFF_AHI +
                    (uint32_t)((wm * 64 + mi * 16 + a_row) * ROWB + h * 32 + a_col);
                ldsm4(&ah[mi * 4], ad);
            }
            #pragma unroll
            for (int f = 0; f < 2; f++) {
                uint32_t wd = base + OFF_WHI +
                    (uint32_t)((wn * 32 + f * 16 + b_row) * ROWB + h * 32 + b_col);
                ldsm4(&bb[f * 4], wd);
            }
            #pragma unroll
            for (int mi = 0; mi < 4; mi++)
                #pragma unroll
                for (int nj = 0; nj < 4; nj++)
                    mma16816(acc[mi][nj], &ah[mi * 4], &bb[(nj >> 1) * 4 + (nj & 1) * 2]);

            #pragma unroll
            for (int mi = 0; mi < 4; mi++) {
                uint32_t ad = base + OFF_ALO +
                    (uint32_t)((wm * 64 + mi * 16 + a_row) * ROWB + h * 32 + a_col);
                ldsm4(&al[mi * 4], ad);
            }
            #pragma unroll
            for (int mi = 0; mi < 4; mi++)
                #pragma unroll
                for (int nj = 0; nj < 4; nj++)
                    mma16816(acc[mi][nj], &al[mi * 4], &bb[(nj >> 1) * 4 + (nj & 1) * 2]);

            #pragma unroll
            for (int f = 0; f < 2; f++) {
                uint32_t wd = base + OFF_WLO +
                    (uint32_t)((wn * 32 + f * 16 + b_row) * ROWB + h * 32 + b_col);
                ldsm4(&bb[f * 4], wd);
            }
            #pragma unroll
            for (int mi = 0; mi < 4; mi++)
                #pragma unroll
                for (int nj = 0; nj < 4; nj++)
                    mma16816(acc[mi][nj], &ah[mi * 4], &bb[(nj >> 1) * 4 + (nj & 1) * 2]);
        }
        __syncthreads();
        if (t + 2 < NCHUNK) load_chunk(t + 2, b);
    }

    // ---- fused LSTM epilogue ----
    // D frag: d0,d1 = row (lane>>2), cols q*2, q*2+1 ; d2,d3 = row +8 (q = lane&3)
    // col offsets within unit: 0=f 1=i 2=o 3=c~ ; q even lane holds (f,i), odd (o,c)
    const bool fi = ((lane & 1) == 0);
    const int q = lane & 3;
    float* ht_base = out + (size_t)B_DIM * H_DIM;

    #pragma unroll
    for (int nj = 0; nj < 4; nj++) {
        const int nb = n0 + wn * 32 + nj * 8 + q * 2;
        const float b0 = g_biasp[nb];
        const float b1 = g_biasp[nb + 1];
        const int u = (n0 >> 2) + wn * 8 + nj * 2 + (q >> 1);
        #pragma unroll
        for (int mi = 0; mi < 4; mi++) {
            const int r = m0 + wm * 64 + mi * 16 + (lane >> 2);
            float z0 = acc[mi][nj][0] + b0;
            float z1 = acc[mi][nj][1] + b1;
            float z2 = acc[mi][nj][2] + b0;
            float z3 = acc[mi][nj][3] + b1;
            // fi lane: (f,i) both sigmoid; oc lane: o=sigmoid, c=tanh
            float v0 = fast_sigmoid(z0);
            float v1 = fi ? fast_sigmoid(z1) : fast_tanh(z1);
            float v2 = fast_sigmoid(z2);
            float v3 = fi ? fast_sigmoid(z3) : fast_tanh(z3);
            // exchange: fi lane sends row+8 (f,i), receives row (o,c);
            //           oc lane sends row (o,c), receives row+8 (f,i)
            float s0 = fi ? v2 : v0;
            float s1 = fi ? v3 : v1;
            float r0 = __shfl_xor_sync(0xffffffffu, s0, 1);
            float r1 = __shfl_xor_sync(0xffffffffu, s1, 1);
            const int row = r + (fi ? 0 : 8);
            float gf = fi ? v0 : r0;
            float gi = fi ? v1 : r1;
            float go = fi ? r0 : v2;
            float gc = fi ? r1 : v3;
            float cp = c_in[(size_t)row * H_DIM + u];
            float ct = gf * cp + gc * gi;
            float ht = fast_tanh(ct) * go;
            out[(size_t)row * H_DIM + u] = ct;
            ht_base[(size_t)row * H_DIM + u] = ht;
        }
    }
}

// ---------------------------------------------------------------------------
// kernel_launch
// Inputs: x, c, h, Wxf, bxf, Whf, bhf, Wxi, bxi, Whi, bhi,
//         Wxo, bxo, Who, bho, Wxc, bxc, Whc, bhc
// ---------------------------------------------------------------------------
extern "C" void kernel_launch(void* const* d_in, const int* in_sizes, int n_in,
                              void* d_out, int out_size) {
    const float* x   = (const float*)d_in[0];
    const float* c   = (const float*)d_in[1];
    const float* h   = (const float*)d_in[2];
    const float* Wxf = (const float*)d_in[3];
    const float* bxf = (const float*)d_in[4];
    const float* Whf = (const float*)d_in[5];
    const float* bhf = (const float*)d_in[6];
    const float* Wxi = (const float*)d_in[7];
    const float* bxi = (const float*)d_in[8];
    const float* Whi = (const float*)d_in[9];
    const float* bhi = (const float*)d_in[10];
    const float* Wxo = (const float*)d_in[11];
    const float* bxo = (const float*)d_in[12];
    const float* Who = (const float*)d_in[13];
    const float* bho = (const float*)d_in[14];
    const float* Wxc = (const float*)d_in[15];
    const float* bxc = (const float*)d_in[16];
    const float* Whc = (const float*)d_in[17];
    const float* bhc = (const float*)d_in[18];

    pack_A_kernel<<<(B_DIM * K_DIM / 4) / 256, 256>>>((const float4*)x, (const float4*)h);
    pack_W_kernel<<<(N_DIM * K_DIM / 4) / 256, 256>>>(
        (const float4*)Wxf, (const float4*)Wxi, (const float4*)Wxo, (const float4*)Wxc,
        (const float4*)Whf, (const float4*)Whi, (const float4*)Who, (const float4*)Whc);
    pack_bias_kernel<<<N_DIM / 256, 256>>>(bxf, bxi, bxo, bxc, bhf, bhi, bho, bhc);

    cudaFuncSetAttribute(lstm_gemm_kernel,
                         cudaFuncAttributeMaxDynamicSharedMemorySize, SMEM_TOTAL);
    dim3 grid(N_DIM / BN, B_DIM / BM);   // (32, 32)
    lstm_gemm_kernel<<<grid, 256, SMEM_TOTAL>>>(c, (float*)d_out);
}

// round 4
// speedup vs baseline: 3.2423x; 1.2309x over previous
#include <cuda_runtime.h>
#include <cuda_fp16.h>
#include <cstdint>
#include <math.h>

#define B_DIM 4096
#define IN_DIM 1024
#define H_DIM 1024
#define K_DIM 2048   // IN + H
#define N_DIM 4096   // 4*H, gate-interleaved: col n -> gate n&3, hidden n>>2

#define BM 128
#define BN 128
#define KC 32
#define NCHUNK (K_DIM / KC)     // 64

// SMEM tile geometry: rows of 32 fp16 (64B) padded to 80B for conflict-free
// ldmatrix (bank start = 20*r mod 32, distinct for r=0..15) and cp.async.
#define ROWB 80
#define TILEB (128 * ROWB)            // 10240 B per matrix
#define OFF_AHI 0
#define OFF_ALO (TILEB)
#define OFF_W   (2 * TILEB)
#define BUFB   (3 * TILEB)            // 30720 B
#define NSTAGE 3
#define SMEM_TOTAL (NSTAGE * BUFB)    // 92160 B

// ---------------------------------------------------------------------------
// Device scratch
// ---------------------------------------------------------------------------
__device__ __half g_Ahi[(size_t)B_DIM * K_DIM];
__device__ __half g_Alo[(size_t)B_DIM * K_DIM];
__device__ __half g_W[(size_t)N_DIM * K_DIM];
__device__ float g_biasp[N_DIM];

// ---------------------------------------------------------------------------
// PTX helpers (baseline PTX only: works on compute_103 virtual arch)
// ---------------------------------------------------------------------------
__device__ __forceinline__ uint32_t smem_u32(const void* p) {
    uint32_t a;
    asm("{ .reg .u64 t; cvta.to.shared.u64 t, %1; cvt.u32.u64 %0, t; }" : "=r"(a) : "l"(p));
    return a;
}
__device__ __forceinline__ void cp_async16(uint32_t dst, const void* src) {
    asm volatile("cp.async.cg.shared.global [%0], [%1], 16;" :: "r"(dst), "l"(src));
}
#define CP_COMMIT()  asm volatile("cp.async.commit_group;" ::: "memory")
#define CP_WAIT(N)   asm volatile("cp.async.wait_group %0;" :: "n"(N) : "memory")

__device__ __forceinline__ void ldsm4(uint32_t* r, uint32_t addr) {
    asm volatile("ldmatrix.sync.aligned.m8n8.x4.shared.b16 {%0,%1,%2,%3}, [%4];"
        : "=r"(r[0]), "=r"(r[1]), "=r"(r[2]), "=r"(r[3]) : "r"(addr));
}
__device__ __forceinline__ void mma16816(float* d, const uint32_t* a, const uint32_t* b) {
    asm volatile("mma.sync.aligned.m16n8k16.row.col.f32.f16.f16.f32 "
        "{%0,%1,%2,%3}, {%4,%5,%6,%7}, {%8,%9}, {%0,%1,%2,%3};"
        : "+f"(d[0]), "+f"(d[1]), "+f"(d[2]), "+f"(d[3])
        : "r"(a[0]), "r"(a[1]), "r"(a[2]), "r"(a[3]), "r"(b[0]), "r"(b[1]));
}

__device__ __forceinline__ float fast_sigmoid(float x) { return 1.0f / (1.0f + __expf(-x)); }
__device__ __forceinline__ float fast_tanh(float x) {
    float e = __expf(-2.0f * fabsf(x));
    return copysignf((1.0f - e) / (1.0f + e), x);
}

// ---------------------------------------------------------------------------
// Pack A = [x | h] into fp16 hi/lo split
// ---------------------------------------------------------------------------
__global__ void pack_A_kernel(const float4* __restrict__ x, const float4* __restrict__ h) {
    int i = blockIdx.x * blockDim.x + threadIdx.x;   // over B*K/4
    int b = i >> 9, k4 = i & 511;
    float4 v = (k4 < 256) ? x[b * 256 + k4] : h[b * 256 + (k4 - 256)];
    float vs[4] = {v.x, v.y, v.z, v.w};
    __half hi[4], lo[4];
    #pragma unroll
    for (int e = 0; e < 4; e++) {
        hi[e] = __float2half(vs[e]);
        lo[e] = __float2half(vs[e] - __half2float(hi[e]));
    }
    __half2* Ah = reinterpret_cast<__half2*>(g_Ahi);
    __half2* Al = reinterpret_cast<__half2*>(g_Alo);
    Ah[i * 2]     = __halves2half2(hi[0], hi[1]);
    Ah[i * 2 + 1] = __halves2half2(hi[2], hi[3]);
    Al[i * 2]     = __halves2half2(lo[0], lo[1]);
    Al[i * 2 + 1] = __halves2half2(lo[2], lo[3]);
}

// ---------------------------------------------------------------------------
// Pack W gate-interleaved (col n -> gate n&3, hidden n>>2), K-concat, fp16
// ---------------------------------------------------------------------------
__global__ void pack_W_kernel(const float4* __restrict__ Wxf, const float4* __restrict__ Wxi,
                              const float4* __restrict__ Wxo, const float4* __restrict__ Wxc,
                              const float4* __restrict__ Whf, const float4* __restrict__ Whi,
                              const float4* __restrict__ Who, const float4* __restrict__ Whc) {
    int i = blockIdx.x * blockDim.x + threadIdx.x;   // over N*K/4
    int n = i >> 9, k4 = i & 511;
    int g = n & 3, j = n >> 2;
    const float4* Wx[4] = {Wxf, Wxi, Wxo, Wxc};
    const float4* Wh[4] = {Whf, Whi, Who, Whc};
    float4 v = (k4 < 256) ? Wx[g][j * 256 + k4] : Wh[g][j * 256 + (k4 - 256)];
    __half2* W2 = reinterpret_cast<__half2*>(g_W);
    W2[i * 2]     = __halves2half2(__float2half(v.x), __float2half(v.y));
    W2[i * 2 + 1] = __halves2half2(__float2half(v.z), __float2half(v.w));
}

__global__ void pack_bias_kernel(const float* __restrict__ bxf, const float* __restrict__ bxi,
                                 const float* __restrict__ bxo, const float* __restrict__ bxc,
                                 const float* __restrict__ bhf, const float* __restrict__ bhi,
                                 const float* __restrict__ bho, const float* __restrict__ bhc) {
    int n = blockIdx.x * blockDim.x + threadIdx.x;
    int g = n & 3, j = n >> 2;
    const float* bx[4] = {bxf, bxi, bxo, bxc};
    const float* bh[4] = {bhf, bhi, bho, bhc};
    g_biasp[n] = bx[g][j] + bh[g][j];
}

// ---------------------------------------------------------------------------
// HMMA GEMM + fused LSTM epilogue.
// 8 warps: warp grid 2(M) x 4(N); warp tile 64x32; mma m16n8k16 fp16.
// acc += Ahi*W + Alo*W (fp32), bias+activations+LSTM in epilogue.
// 3-stage cp.async pipeline.
// ---------------------------------------------------------------------------
__global__ void __launch_bounds__(256, 2)
lstm_gemm_kernel(const float* __restrict__ c_in, float* __restrict__ out) {
    extern __shared__ char smem[];
    const uint32_t sb = smem_u32(smem);
    const int tid  = threadIdx.x;
    const int lane = tid & 31;
    const int wid  = tid >> 5;
    const int wm   = wid >> 2;         // 0..1
    const int wn   = wid & 3;          // 0..3
    const int m0   = blockIdx.y * BM;
    const int n0   = blockIdx.x * BN;

    // ---- chunk loader: 6 x 16B cp.async per thread ----
    auto load_chunk = [&](int t, int b) {
        const uint32_t base = sb + b * BUFB;
        const int r = tid >> 2;            // 0..63
        const int s = tid & 3;             // 0..3 (16B segment)
        const int kg = t * KC + s * 8;     // global k of this segment
        #pragma unroll
        for (int q = 0; q < 2; q++) {      // rows r and r+64
            const int rr = r + q * 64;
            const uint32_t so = (uint32_t)(rr * ROWB + s * 16);
            const size_t aoff = (size_t)(m0 + rr) * K_DIM + kg;
            const size_t woff = (size_t)(n0 + rr) * K_DIM + kg;
            cp_async16(base + OFF_AHI + so, g_Ahi + aoff);
            cp_async16(base + OFF_ALO + so, g_Alo + aoff);
            cp_async16(base + OFF_W   + so, g_W   + woff);
        }
        CP_COMMIT();
    };

    float acc[4][4][4];
    #pragma unroll
    for (int i = 0; i < 4; i++)
        #pragma unroll
        for (int j = 0; j < 4; j++)
            #pragma unroll
            for (int e = 0; e < 4; e++) acc[i][j][e] = 0.0f;

    load_chunk(0, 0);
    load_chunk(1, 1);
    load_chunk(2, 2);

    // ldmatrix lane addressing (within a 16x16 fp16 fragment)
    const int a_row = lane & 15;                 // A: row within 16
    const int a_col = (lane >> 4) * 16;          // byte offset: 8-col half
    const int b_row = (lane & 7) + (lane >> 4) * 8;   // W(n) row within 16
    const int b_col = ((lane >> 3) & 1) * 16;         // byte offset: k half

    int buf = 0;
    for (int t = 0; t < NCHUNK; t++) {
        if (t + 3 <= NCHUNK - 1)      CP_WAIT(2);
        else if (t + 2 <= NCHUNK - 1) CP_WAIT(1);
        else                          CP_WAIT(0);
        __syncthreads();

        const uint32_t base = sb + buf * BUFB;
        #pragma unroll
        for (int h = 0; h < 2; h++) {            // two k16 steps per 32-chunk
            uint32_t ah[16], al[16], bb[8];
            #pragma unroll
            for (int mi = 0; mi < 4; mi++) {
                uint32_t ad = base + OFF_AHI +
                    (uint32_t)((wm * 64 + mi * 16 + a_row) * ROWB + h * 32 + a_col);
                ldsm4(&ah[mi * 4], ad);
            }
            #pragma unroll
            for (int f = 0; f < 2; f++) {
                uint32_t wd = base + OFF_W +
                    (uint32_t)((wn * 32 + f * 16 + b_row) * ROWB + h * 32 + b_col);
                ldsm4(&bb[f * 4], wd);
            }
            #pragma unroll
            for (int mi = 0; mi < 4; mi++) {
                uint32_t ad = base + OFF_ALO +
                    (uint32_t)((wm * 64 + mi * 16 + a_row) * ROWB + h * 32 + a_col);
                ldsm4(&al[mi * 4], ad);
            }
            #pragma unroll
            for (int mi = 0; mi < 4; mi++)
                #pragma unroll
                for (int nj = 0; nj < 4; nj++)
                    mma16816(acc[mi][nj], &ah[mi * 4], &bb[(nj >> 1) * 4 + (nj & 1) * 2]);
            #pragma unroll
            for (int mi = 0; mi < 4; mi++)
                #pragma unroll
                for (int nj = 0; nj < 4; nj++)
                    mma16816(acc[mi][nj], &al[mi * 4], &bb[(nj >> 1) * 4 + (nj & 1) * 2]);
        }
        __syncthreads();
        if (t + 3 < NCHUNK) load_chunk(t + 3, buf);
        buf = (buf == NSTAGE - 1) ? 0 : buf + 1;
    }

    // ---- fused LSTM epilogue ----
    // D frag: d0,d1 = row (lane>>2), cols q*2, q*2+1 ; d2,d3 = row +8 (q = lane&3)
    // col offsets within unit: 0=f 1=i 2=o 3=c~ ; q even lane holds (f,i), odd (o,c)
    const bool fi = ((lane & 1) == 0);
    const int q = lane & 3;
    float* ht_base = out + (size_t)B_DIM * H_DIM;

    #pragma unroll
    for (int nj = 0; nj < 4; nj++) {
        const int nb = n0 + wn * 32 + nj * 8 + q * 2;
        const float b0 = g_biasp[nb];
        const float b1 = g_biasp[nb + 1];
        const int u = (n0 >> 2) + wn * 8 + nj * 2 + (q >> 1);
        #pragma unroll
        for (int mi = 0; mi < 4; mi++) {
            const int r = m0 + wm * 64 + mi * 16 + (lane >> 2);
            float z0 = acc[mi][nj][0] + b0;
            float z1 = acc[mi][nj][1] + b1;
            float z2 = acc[mi][nj][2] + b0;
            float z3 = acc[mi][nj][3] + b1;
            // fi lane: (f,i) both sigmoid; oc lane: o=sigmoid, c=tanh
            float v0 = fast_sigmoid(z0);
            float v1 = fi ? fast_sigmoid(z1) : fast_tanh(z1);
            float v2 = fast_sigmoid(z2);
            float v3 = fi ? fast_sigmoid(z3) : fast_tanh(z3);
            // exchange: fi lane sends row+8 (f,i), receives row (o,c);
            //           oc lane sends row (o,c), receives row+8 (f,i)
            float s0 = fi ? v2 : v0;
            float s1 = fi ? v3 : v1;
            float r0 = __shfl_xor_sync(0xffffffffu, s0, 1);
            float r1 = __shfl_xor_sync(0xffffffffu, s1, 1);
            const int row = r + (fi ? 0 : 8);
            float gf = fi ? v0 : r0;
            float gi = fi ? v1 : r1;
            float go = fi ? r0 : v2;
            float gc = fi ? r1 : v3;
            float cp = c_in[(size_t)row * H_DIM + u];
            float ct = gf * cp + gc * gi;
            float ht = fast_tanh(ct) * go;
            out[(size_t)row * H_DIM + u] = ct;
            ht_base[(size_t)row * H_DIM + u] = ht;
        }
    }
}

// ---------------------------------------------------------------------------
// kernel_launch
// Inputs: x, c, h, Wxf, bxf, Whf, bhf, Wxi, bxi, Whi, bhi,
//         Wxo, bxo, Who, bho, Wxc, bxc, Whc, bhc
// ---------------------------------------------------------------------------
extern "C" void kernel_launch(void* const* d_in, const int* in_sizes, int n_in,
                              void* d_out, int out_size) {
    const float* x   = (const float*)d_in[0];
    const float* c   = (const float*)d_in[1];
    const float* h   = (const float*)d_in[2];
    const float* Wxf = (const float*)d_in[3];
    const float* bxf = (const float*)d_in[4];
    const float* Whf = (const float*)d_in[5];
    const float* bhf = (const float*)d_in[6];
    const float* Wxi = (const float*)d_in[7];
    const float* bxi = (const float*)d_in[8];
    const float* Whi = (const float*)d_in[9];
    const float* bhi = (const float*)d_in[10];
    const float* Wxo = (const float*)d_in[11];
    const float* bxo = (const float*)d_in[12];
    const float* Who = (const float*)d_in[13];
    const float* bho = (const float*)d_in[14];
    const float* Wxc = (const float*)d_in[15];
    const float* bxc = (const float*)d_in[16];
    const float* Whc = (const float*)d_in[17];
    const float* bhc = (const float*)d_in[18];

    pack_A_kernel<<<(B_DIM * K_DIM / 4) / 256, 256>>>((const float4*)x, (const float4*)h);
    pack_W_kernel<<<(N_DIM * K_DIM / 4) / 256, 256>>>(
        (const float4*)Wxf, (const float4*)Wxi, (const float4*)Wxo, (const float4*)Wxc,
        (const float4*)Whf, (const float4*)Whi, (const float4*)Who, (const float4*)Whc);
    pack_bias_kernel<<<N_DIM / 256, 256>>>(bxf, bxi, bxo, bxc, bhf, bhi, bho, bhc);

    cudaFuncSetAttribute(lstm_gemm_kernel,
                         cudaFuncAttributeMaxDynamicSharedMemorySize, SMEM_TOTAL);
    dim3 grid(N_DIM / BN, B_DIM / BM);   // (32, 32)
    lstm_gemm_kernel<<<grid, 256, SMEM_TOTAL>>>(c, (float*)d_out);
}

// round 5
// speedup vs baseline: 5.9266x; 1.8279x over previous
#include <cuda_runtime.h>
#include <cuda_fp16.h>
#include <cstdint>
#include <math.h>

#define B_DIM 4096
#define IN_DIM 1024
#define H_DIM 1024
#define K_DIM 2048   // IN + H
#define N_DIM 4096   // 4*H, gate-interleaved: col n -> gate n&3, hidden n>>2

#define BM 128
#define BN 128
#define KC 32
#define NCHUNK (K_DIM / KC)     // 64

// SMEM tile geometry: rows of 32 fp16 (64B) padded to 80B for conflict-free
// ldmatrix (bank start = 20*r mod 32, distinct for r=0..15) and cp.async.
#define ROWB 80
#define TILEB (128 * ROWB)            // 10240 B per matrix
#define OFF_A 0
#define OFF_W (TILEB)
#define BUFB  (2 * TILEB)             // 20480 B per stage
#define NSTAGE 4
#define SMEM_TOTAL (NSTAGE * BUFB)    // 81920 B

// ---------------------------------------------------------------------------
// Device scratch
// ---------------------------------------------------------------------------
__device__ __half g_A[(size_t)B_DIM * K_DIM];
__device__ __half g_W[(size_t)N_DIM * K_DIM];
__device__ float g_biasp[N_DIM];

// ---------------------------------------------------------------------------
// PTX helpers (baseline PTX only: works on compute_103 virtual arch)
// ---------------------------------------------------------------------------
__device__ __forceinline__ uint32_t smem_u32(const void* p) {
    uint32_t a;
    asm("{ .reg .u64 t; cvta.to.shared.u64 t, %1; cvt.u32.u64 %0, t; }" : "=r"(a) : "l"(p));
    return a;
}
__device__ __forceinline__ void cp_async16(uint32_t dst, const void* src) {
    asm volatile("cp.async.cg.shared.global [%0], [%1], 16;" :: "r"(dst), "l"(src));
}
#define CP_COMMIT()  asm volatile("cp.async.commit_group;" ::: "memory")
#define CP_WAIT(N)   asm volatile("cp.async.wait_group %0;" :: "n"(N) : "memory")

__device__ __forceinline__ void ldsm4(uint32_t* r, uint32_t addr) {
    asm volatile("ldmatrix.sync.aligned.m8n8.x4.shared.b16 {%0,%1,%2,%3}, [%4];"
        : "=r"(r[0]), "=r"(r[1]), "=r"(r[2]), "=r"(r[3]) : "r"(addr));
}
__device__ __forceinline__ void mma16816(float* d, const uint32_t* a, const uint32_t* b) {
    asm volatile("mma.sync.aligned.m16n8k16.row.col.f32.f16.f16.f32 "
        "{%0,%1,%2,%3}, {%4,%5,%6,%7}, {%8,%9}, {%0,%1,%2,%3};"
        : "+f"(d[0]), "+f"(d[1]), "+f"(d[2]), "+f"(d[3])
        : "r"(a[0]), "r"(a[1]), "r"(a[2]), "r"(a[3]), "r"(b[0]), "r"(b[1]));
}

__device__ __forceinline__ float fast_sigmoid(float x) { return 1.0f / (1.0f + __expf(-x)); }
__device__ __forceinline__ float fast_tanh(float x) {
    float e = __expf(-2.0f * fabsf(x));
    return copysignf((1.0f - e) / (1.0f + e), x);
}

// ---------------------------------------------------------------------------
// Pack A = [x | h] fp16
// ---------------------------------------------------------------------------
__global__ void pack_A_kernel(const float4* __restrict__ x, const float4* __restrict__ h) {
    int i = blockIdx.x * blockDim.x + threadIdx.x;   // over B*K/4
    int b = i >> 9, k4 = i & 511;
    float4 v = (k4 < 256) ? x[b * 256 + k4] : h[b * 256 + (k4 - 256)];
    __half2* A2 = reinterpret_cast<__half2*>(g_A);
    A2[i * 2]     = __halves2half2(__float2half(v.x), __float2half(v.y));
    A2[i * 2 + 1] = __halves2half2(__float2half(v.z), __float2half(v.w));
}

// ---------------------------------------------------------------------------
// Pack W gate-interleaved (col n -> gate n&3, hidden n>>2), K-concat, fp16
// ---------------------------------------------------------------------------
__global__ void pack_W_kernel(const float4* __restrict__ Wxf, const float4* __restrict__ Wxi,
                              const float4* __restrict__ Wxo, const float4* __restrict__ Wxc,
                              const float4* __restrict__ Whf, const float4* __restrict__ Whi,
                              const float4* __restrict__ Who, const float4* __restrict__ Whc) {
    int i = blockIdx.x * blockDim.x + threadIdx.x;   // over N*K/4
    int n = i >> 9, k4 = i & 511;
    int g = n & 3, j = n >> 2;
    const float4* Wx[4] = {Wxf, Wxi, Wxo, Wxc};
    const float4* Wh[4] = {Whf, Whi, Who, Whc};
    float4 v = (k4 < 256) ? Wx[g][j * 256 + k4] : Wh[g][j * 256 + (k4 - 256)];
    __half2* W2 = reinterpret_cast<__half2*>(g_W);
    W2[i * 2]     = __halves2half2(__float2half(v.x), __float2half(v.y));
    W2[i * 2 + 1] = __halves2half2(__float2half(v.z), __float2half(v.w));
}

__global__ void pack_bias_kernel(const float* __restrict__ bxf, const float* __restrict__ bxi,
                                 const float* __restrict__ bxo, const float* __restrict__ bxc,
                                 const float* __restrict__ bhf, const float* __restrict__ bhi,
                                 const float* __restrict__ bho, const float* __restrict__ bhc) {
    int n = blockIdx.x * blockDim.x + threadIdx.x;
    int g = n & 3, j = n >> 2;
    const float* bx[4] = {bxf, bxi, bxo, bxc};
    const float* bh[4] = {bhf, bhi, bho, bhc};
    g_biasp[n] = bx[g][j] + bh[g][j];
}

// ---------------------------------------------------------------------------
// HMMA GEMM + fused LSTM epilogue.
// 8 warps: warp grid 2(M) x 4(N); warp tile 64x32; mma m16n8k16 fp16.
// 4-stage cp.async pipeline, ONE __syncthreads per k-chunk.
// ---------------------------------------------------------------------------
__global__ void __launch_bounds__(256, 2)
lstm_gemm_kernel(const float* __restrict__ c_in, float* __restrict__ out) {
    extern __shared__ char smem[];
    const uint32_t sb = smem_u32(smem);
    const int tid  = threadIdx.x;
    const int lane = tid & 31;
    const int wid  = tid >> 5;
    const int wm   = wid >> 2;         // 0..1
    const int wn   = wid & 3;          // 0..3
    const int m0   = blockIdx.y * BM;
    const int n0   = blockIdx.x * BN;

    // ---- chunk loader: 4 x 16B cp.async per thread ----
    auto load_chunk = [&](int t, int b) {
        const uint32_t base = sb + b * BUFB;
        const int r = tid >> 2;            // 0..63
        const int s = tid & 3;             // 0..3 (16B segment)
        const int kg = t * KC + s * 8;     // global k of this segment
        #pragma unroll
        for (int q = 0; q < 2; q++) {      // rows r and r+64
            const int rr = r + q * 64;
            const uint32_t so = (uint32_t)(rr * ROWB + s * 16);
            cp_async16(base + OFF_A + so, g_A + (size_t)(m0 + rr) * K_DIM + kg);
            cp_async16(base + OFF_W + so, g_W + (size_t)(n0 + rr) * K_DIM + kg);
        }
        CP_COMMIT();
    };

    float acc[4][4][4];
    #pragma unroll
    for (int i = 0; i < 4; i++)
        #pragma unroll
        for (int j = 0; j < 4; j++)
            #pragma unroll
            for (int e = 0; e < 4; e++) acc[i][j][e] = 0.0f;

    // Prologue: fill NSTAGE-1 = 3 stages
    load_chunk(0, 0);
    load_chunk(1, 1);
    load_chunk(2, 2);

    // ldmatrix lane addressing (within a 16x16 fp16 fragment)
    const int a_row = lane & 15;                 // A: row within 16
    const int a_col = (lane >> 4) * 16;          // byte offset: 8-col half
    const int b_row = (lane & 7) + (lane >> 4) * 8;   // W(n) row within 16
    const int b_col = ((lane >> 3) & 1) * 16;         // byte offset: k half

    for (int t = 0; t < NCHUNK; t++) {
        if (t < NCHUNK - 2)       CP_WAIT(2);
        else if (t == NCHUNK - 2) CP_WAIT(1);
        else                      CP_WAIT(0);
        __syncthreads();   // chunk t visible to all; stage (t-1)%4 free for reuse

        const uint32_t base = sb + (t & (NSTAGE - 1)) * BUFB;
        #pragma unroll
        for (int h = 0; h < 2; h++) {            // two k16 steps per 32-chunk
            uint32_t ah[16], bb[8];
            #pragma unroll
            for (int mi = 0; mi < 4; mi++) {
                uint32_t ad = base + OFF_A +
                    (uint32_t)((wm * 64 + mi * 16 + a_row) * ROWB + h * 32 + a_col);
                ldsm4(&ah[mi * 4], ad);
            }
            #pragma unroll
            for (int f = 0; f < 2; f++) {
                uint32_t wd = base + OFF_W +
                    (uint32_t)((wn * 32 + f * 16 + b_row) * ROWB + h * 32 + b_col);
                ldsm4(&bb[f * 4], wd);
            }
            #pragma unroll
            for (int mi = 0; mi < 4; mi++)
                #pragma unroll
                for (int nj = 0; nj < 4; nj++)
                    mma16816(acc[mi][nj], &ah[mi * 4], &bb[(nj >> 1) * 4 + (nj & 1) * 2]);
        }
        // Load chunk t+3 into stage (t+3)%4 = (t-1)%4, freed by the barrier above.
        if (t + 3 < NCHUNK) load_chunk(t + 3, (t + 3) & (NSTAGE - 1));
    }

    // ---- fused LSTM epilogue ----
    // D frag: d0,d1 = row (lane>>2), cols q*2, q*2+1 ; d2,d3 = row +8 (q = lane&3)
    // col offsets within unit: 0=f 1=i 2=o 3=c~ ; q even lane holds (f,i), odd (o,c)
    const bool fi = ((lane & 1) == 0);
    const int q = lane & 3;
    float* ht_base = out + (size_t)B_DIM * H_DIM;

    #pragma unroll
    for (int nj = 0; nj < 4; nj++) {
        const int nb = n0 + wn * 32 + nj * 8 + q * 2;
        const float b0 = g_biasp[nb];
        const float b1 = g_biasp[nb + 1];
        const int u = (n0 >> 2) + wn * 8 + nj * 2 + (q >> 1);
        #pragma unroll
        for (int mi = 0; mi < 4; mi++) {
            const int r = m0 + wm * 64 + mi * 16 + (lane >> 2);
            float z0 = acc[mi][nj][0] + b0;
            float z1 = acc[mi][nj][1] + b1;
            float z2 = acc[mi][nj][2] + b0;
            float z3 = acc[mi][nj][3] + b1;
            // fi lane: (f,i) both sigmoid; oc lane: o=sigmoid, c=tanh
            float v0 = fast_sigmoid(z0);
            float v1 = fi ? fast_sigmoid(z1) : fast_tanh(z1);
            float v2 = fast_sigmoid(z2);
            float v3 = fi ? fast_sigmoid(z3) : fast_tanh(z3);
            // exchange: fi lane sends row+8 (f,i), receives row (o,c);
            //           oc lane sends row (o,c), receives row+8 (f,i)
            float s0 = fi ? v2 : v0;
            float s1 = fi ? v3 : v1;
            float r0 = __shfl_xor_sync(0xffffffffu, s0, 1);
            float r1 = __shfl_xor_sync(0xffffffffu, s1, 1);
            const int row = r + (fi ? 0 : 8);
            float gf = fi ? v0 : r0;
            float gi = fi ? v1 : r1;
            float go = fi ? r0 : v2;
            float gc = fi ? r1 : v3;
            float cp = c_in[(size_t)row * H_DIM + u];
            float ct = gf * cp + gc * gi;
            float ht = fast_tanh(ct) * go;
            out[(size_t)row * H_DIM + u] = ct;
            ht_base[(size_t)row * H_DIM + u] = ht;
        }
    }
}

// ---------------------------------------------------------------------------
// kernel_launch
// Inputs: x, c, h, Wxf, bxf, Whf, bhf, Wxi, bxi, Whi, bhi,
//         Wxo, bxo, Who, bho, Wxc, bxc, Whc, bhc
// ---------------------------------------------------------------------------
extern "C" void kernel_launch(void* const* d_in, const int* in_sizes, int n_in,
                              void* d_out, int out_size) {
    const float* x   = (const float*)d_in[0];
    const float* c   = (const float*)d_in[1];
    const float* h   = (const float*)d_in[2];
    const float* Wxf = (const float*)d_in[3];
    const float* bxf = (const float*)d_in[4];
    const float* Whf = (const float*)d_in[5];
    const float* bhf = (const float*)d_in[6];
    const float* Wxi = (const float*)d_in[7];
    const float* bxi = (const float*)d_in[8];
    const float* Whi = (const float*)d_in[9];
    const float* bhi = (const float*)d_in[10];
    const float* Wxo = (const float*)d_in[11];
    const float* bxo = (const float*)d_in[12];
    const float* Who = (const float*)d_in[13];
    const float* bho = (const float*)d_in[14];
    const float* Wxc = (const float*)d_in[15];
    const float* bxc = (const float*)d_in[16];
    const float* Whc = (const float*)d_in[17];
    const float* bhc = (const float*)d_in[18];

    pack_A_kernel<<<(B_DIM * K_DIM / 4) / 256, 256>>>((const float4*)x, (const float4*)h);
    pack_W_kernel<<<(N_DIM * K_DIM / 4) / 256, 256>>>(
        (const float4*)Wxf, (const float4*)Wxi, (const float4*)Wxo, (const float4*)Wxc,
        (const float4*)Whf, (const float4*)Whi, (const float4*)Who, (const float4*)Whc);
    pack_bias_kernel<<<N_DIM / 256, 256>>>(bxf, bxi, bxo, bxc, bhf, bhi, bho, bhc);

    cudaFuncSetAttribute(lstm_gemm_kernel,
                         cudaFuncAttributeMaxDynamicSharedMemorySize, SMEM_TOTAL);
    dim3 grid(N_DIM / BN, B_DIM / BM);   // (32, 32)
    lstm_gemm_kernel<<<grid, 256, SMEM_TOTAL>>>(c, (float*)d_out);
}